// round 2
// baseline (speedup 1.0000x reference)
#include <cuda_runtime.h>
#include <cstdint>
#include <math.h>

// Problem constants
#define Bz   32
#define SQ   2048
#define SKV  2048
#define Dd   128
#define BM   64
#define BN   64
#define NT   256

#define TOTAL_ELEMS 134217728u           // Bz*SQ*SKV = 2^27
#define TOTAL_WORDS 4194304u             // TOTAL/32

#define SQT_S 68                         // sQt/sKt row stride (floats), mult of 4 for LDS.128
#define SPT_S 65                         // sPt row stride

// 16 MB static dropout bitmask (allocation-free scratch)
__device__ uint32_t g_mask[TOTAL_WORDS];

// ---------------------------------------------------------------------------
// Threefry-2x32, 20 rounds, key = (0, 42)  (jax.random.key(42))
// Verified against Random123 KAT.
// ---------------------------------------------------------------------------
__device__ __forceinline__ void threefry_0_42(uint32_t x0, uint32_t x1,
                                              uint32_t& y0, uint32_t& y1) {
    const uint32_t ks0 = 0u;
    const uint32_t ks1 = 42u;
    const uint32_t ks2 = 0x1BD11BDAu ^ 0u ^ 42u;   // 0x1BD11BF0
    x0 += ks0; x1 += ks1;
#define TF_R(r) { x0 += x1; x1 = __funnelshift_l(x1, x1, (r)); x1 ^= x0; }
    TF_R(13) TF_R(15) TF_R(26) TF_R(6)
    x0 += ks1; x1 += ks2 + 1u;
    TF_R(17) TF_R(29) TF_R(16) TF_R(24)
    x0 += ks2; x1 += ks0 + 2u;
    TF_R(13) TF_R(15) TF_R(26) TF_R(6)
    x0 += ks0; x1 += ks1 + 3u;
    TF_R(17) TF_R(29) TF_R(16) TF_R(24)
    x0 += ks1; x1 += ks2 + 4u;
    TF_R(13) TF_R(15) TF_R(26) TF_R(6)
    x0 += ks2; x1 += ks0 + 5u;
#undef TF_R
    y0 = x0; y1 = x1;
}

__device__ __forceinline__ bool jax_keep(uint32_t bits) {
    // uniform = bitcast((bits>>9) | 0x3F800000) - 1.0 ;  keep = uniform < 0.7f
    float u = __uint_as_float((bits >> 9) | 0x3F800000u) - 1.0f;
    return u < 0.7f;
}

// ---------------------------------------------------------------------------
// Mask kernel — jax_threefry_partitionable (default True in modern JAX):
// per element e (64-bit flat index, here < 2^32):
//   (y0, y1) = threefry(key=(0,42), ctr=(hi32(e)=0, lo32(e)=e))
//   bits[e]  = y0 ^ y1          (32-bit xor-fold)
//   keep     = f32-uniform(bits) < 0.7
// Each thread packs one 32-element mask word.
// ---------------------------------------------------------------------------
__global__ __launch_bounds__(256, 4) void dropout_mask_kernel() {
    uint32_t t = blockIdx.x * 256u + threadIdx.x;   // [0, TOTAL_WORDS)
    uint32_t base = t * 32u;
    uint32_t w = 0u;
#pragma unroll 8
    for (int i = 0; i < 32; ++i) {
        uint32_t y0, y1;
        threefry_0_42(0u, base + (uint32_t)i, y0, y1);
        w |= (uint32_t)jax_keep(y0 ^ y1) << i;
    }
    g_mask[t] = w;
}

// ---------------------------------------------------------------------------
// Flash-attention fp32 kernel. One CTA = (batch b, 64 q-rows). 256 threads.
// Thread (tm,tn) = (tid/16, tid%16): S tile rows 4tm+i, cols 4tn+j;
// O tile rows 4tm+i, cols 8tn+j2.
// ---------------------------------------------------------------------------
__global__ __launch_bounds__(256, 1) void attn_kernel(
    const float* __restrict__ q, const float* __restrict__ k,
    const float* __restrict__ v, const float* __restrict__ sf,
    float* __restrict__ out) {

    extern __shared__ float smem[];
    float* sQt = smem;                          // [128][68] transposed Q (pre-scaled)
    float* sKt = sQt + Dd * SQT_S;              // [128][68] transposed K
    float* sV  = sKt + Dd * SQT_S;              // [64][128] row-major V
    float* sPt = sV + BN * Dd;                  // [64][65]  transposed masked P
    uint32_t* sMask = (uint32_t*)(sPt + BN * SPT_S);  // [64*2] mask words

    const int b  = blockIdx.y;
    const int q0 = blockIdx.x * BM;
    const int tid = threadIdx.x;
    const int tm = tid >> 4;
    const int tn = tid & 15;
    const float scale = sf[b];

    // Load Q tile (scaled by scale_factor), transposed. Coalesced scalar LDG.
    {
        const float* qb = q + ((size_t)b * SQ + q0) * Dd;
#pragma unroll 8
        for (int it = 0; it < 32; ++it) {
            int idx = it * NT + tid;            // 0..8191
            int row = idx >> 7;                 // 0..63
            int d   = idx & 127;
            sQt[d * SQT_S + row] = qb[idx] * scale;
        }
    }

    float m_i[4], l_i[4], acc[4][8];
#pragma unroll
    for (int i = 0; i < 4; ++i) {
        m_i[i] = -INFINITY; l_i[i] = 0.f;
#pragma unroll
        for (int j = 0; j < 8; ++j) acc[i][j] = 0.f;
    }

    const int maskRowBase = (b * SQ + q0) * (SKV / 32);

    for (int kv0 = 0; kv0 < SKV; kv0 += BN) {
        __syncthreads();   // previous PV done reading sKt/sV/sPt (also covers Q load on iter 0)

        // Load K tile transposed (coalesced scalar LDG)
        {
            const float* kb = k + ((size_t)b * SKV + kv0) * Dd;
#pragma unroll 8
            for (int it = 0; it < 32; ++it) {
                int idx = it * NT + tid;
                int row = idx >> 7;
                int d   = idx & 127;
                sKt[d * SQT_S + row] = kb[idx];
            }
        }
        // Load V tile row-major (vectorized, conflict-free)
        {
            const float* vb = v + ((size_t)b * SKV + kv0) * Dd;
#pragma unroll
            for (int it = 0; it < 8; ++it) {
                int idx = it * NT + tid;        // 0..2047 float4s
                int row = idx >> 5;
                int d4  = (idx & 31) << 2;
                *(float4*)(sV + row * Dd + d4) = *(const float4*)(vb + row * Dd + d4);
            }
        }
        // Load mask words for this tile: 64 rows x 2 words
        if (tid < BM * 2) {
            int r = tid >> 1, g = tid & 1;
            sMask[tid] = g_mask[maskRowBase + r * (SKV / 32) + (kv0 >> 5) + g];
        }
        __syncthreads();

        // ---- S = (Q*sf) @ K^T  (fp32) ----
        float s[4][4];
#pragma unroll
        for (int i = 0; i < 4; ++i)
#pragma unroll
            for (int j = 0; j < 4; ++j) s[i][j] = 0.f;

#pragma unroll 4
        for (int d = 0; d < Dd; ++d) {
            float4 a4 = *(const float4*)(sQt + d * SQT_S + (tm << 2));
            float4 b4 = *(const float4*)(sKt + d * SQT_S + (tn << 2));
            float a[4] = {a4.x, a4.y, a4.z, a4.w};
            float bb[4] = {b4.x, b4.y, b4.z, b4.w};
#pragma unroll
            for (int i = 0; i < 4; ++i)
#pragma unroll
                for (int j = 0; j < 4; ++j)
                    s[i][j] = fmaf(a[i], bb[j], s[i][j]);
        }

        // ---- online softmax + dropout mask, write masked P^T to smem ----
#pragma unroll
        for (int i = 0; i < 4; ++i) {
            float mx = fmaxf(fmaxf(s[i][0], s[i][1]), fmaxf(s[i][2], s[i][3]));
#pragma unroll
            for (int off = 1; off < 16; off <<= 1)
                mx = fmaxf(mx, __shfl_xor_sync(0xffffffffu, mx, off, 16));
            float mnew = fmaxf(m_i[i], mx);
            float factor = __expf(m_i[i] - mnew);
            float rs = 0.f;
#pragma unroll
            for (int j = 0; j < 4; ++j) {
                float p = __expf(s[i][j] - mnew);
                s[i][j] = p;
                rs += p;
            }
#pragma unroll
            for (int off = 1; off < 16; off <<= 1)
                rs += __shfl_xor_sync(0xffffffffu, rs, off, 16);
            l_i[i] = l_i[i] * factor + rs;
            m_i[i] = mnew;
#pragma unroll
            for (int j2 = 0; j2 < 8; ++j2) acc[i][j2] *= factor;

            uint32_t word = sMask[((tm << 2) + i) * 2 + (tn >> 3)];
#pragma unroll
            for (int j = 0; j < 4; ++j) {
                int cl = (tn << 2) + j;                       // 0..63
                bool keep = (word >> (cl & 31)) & 1u;
                sPt[cl * SPT_S + (tm << 2) + i] = keep ? s[i][j] : 0.f;
            }
        }
        __syncthreads();

        // ---- acc += P_masked @ V ----
#pragma unroll 2
        for (int n = 0; n < BN; ++n) {
            float a0 = sPt[n * SPT_S + (tm << 2) + 0];
            float a1 = sPt[n * SPT_S + (tm << 2) + 1];
            float a2 = sPt[n * SPT_S + (tm << 2) + 2];
            float a3 = sPt[n * SPT_S + (tm << 2) + 3];
            float4 v0 = *(const float4*)(sV + n * Dd + (tn << 3));
            float4 v1 = *(const float4*)(sV + n * Dd + (tn << 3) + 4);
            float bv[8] = {v0.x, v0.y, v0.z, v0.w, v1.x, v1.y, v1.z, v1.w};
            float a[4] = {a0, a1, a2, a3};
#pragma unroll
            for (int i = 0; i < 4; ++i)
#pragma unroll
                for (int j2 = 0; j2 < 8; ++j2)
                    acc[i][j2] = fmaf(a[i], bv[j2], acc[i][j2]);
        }
    }

    // ---- epilogue: out = acc / (l * 0.7) ----
#pragma unroll
    for (int i = 0; i < 4; ++i) {
        float inv = 1.0f / (l_i[i] * 0.7f);
        int row = q0 + (tm << 2) + i;
        float* ob = out + ((size_t)b * SQ + row) * Dd + (tn << 3);
        float4 o0 = make_float4(acc[i][0] * inv, acc[i][1] * inv,
                                acc[i][2] * inv, acc[i][3] * inv);
        float4 o1 = make_float4(acc[i][4] * inv, acc[i][5] * inv,
                                acc[i][6] * inv, acc[i][7] * inv);
        *(float4*)(ob)     = o0;
        *(float4*)(ob + 4) = o1;
    }
}

// ---------------------------------------------------------------------------
extern "C" void kernel_launch(void* const* d_in, const int* in_sizes, int n_in,
                              void* d_out, int out_size) {
    const float* q  = (const float*)d_in[0];
    const float* k  = (const float*)d_in[1];
    const float* v  = (const float*)d_in[2];
    const float* sf = (const float*)d_in[3];
    float* out = (float*)d_out;

    // 1) Deterministic dropout bitmask (jax partitionable threefry, key 42)
    dropout_mask_kernel<<<TOTAL_WORDS / 256, 256>>>();

    // 2) Flash attention
    size_t smem_bytes = (size_t)(Dd * SQT_S + Dd * SQT_S + BN * Dd + BN * SPT_S) * 4
                        + (size_t)(BM * 2) * 4;
    cudaFuncSetAttribute(attn_kernel, cudaFuncAttributeMaxDynamicSharedMemorySize,
                         (int)smem_bytes);
    dim3 grid(SQ / BM, Bz);
    attn_kernel<<<grid, NT, smem_bytes>>>(q, k, v, sf, out);
}

// round 3
// speedup vs baseline: 1.6375x; 1.6375x over previous
#include <cuda_runtime.h>
#include <cstdint>
#include <math.h>

#define Bz   32
#define SQ   2048
#define SKV  2048
#define Dd   128
#define BM   64
#define BN   128
#define NT   256

#define QS 68      // sQt stride [d][row64]
#define KS 132     // sKt stride [d][col128]
#define VS 132     // sV  stride [n][d128]
#define PS 68      // sPt stride [col128][row64]

typedef unsigned long long u64;
typedef unsigned int u32;

// ---------------- f32x2 packed helpers ----------------
__device__ __forceinline__ u64 ffma2(u64 a, u64 b, u64 c) {
    u64 d; asm("fma.rn.f32x2 %0, %1, %2, %3;" : "=l"(d) : "l"(a), "l"(b), "l"(c));
    return d;
}
__device__ __forceinline__ u64 fmul2(u64 a, u64 b) {
    u64 d; asm("mul.rn.f32x2 %0, %1, %2;" : "=l"(d) : "l"(a), "l"(b));
    return d;
}
__device__ __forceinline__ u64 pk2(float lo, float hi) {
    u64 d; asm("mov.b64 %0, {%1, %2};" : "=l"(d)
               : "r"(__float_as_uint(lo)), "r"(__float_as_uint(hi)));
    return d;
}
__device__ __forceinline__ void upk2(u64 v, float& lo, float& hi) {
    u32 a, b; asm("mov.b64 {%0, %1}, %2;" : "=r"(a), "=r"(b) : "l"(v));
    lo = __uint_as_float(a); hi = __uint_as_float(b);
}

// ---------------- Threefry-2x32-20, key=(0,42) ----------------
__device__ __forceinline__ void threefry_0_42(u32 x0, u32 x1, u32& y0, u32& y1) {
    const u32 ks1 = 42u;
    const u32 ks2 = 0x1BD11BDAu ^ 42u;
    x1 += ks1;
#define TF_R(r) { x0 += x1; x1 = __funnelshift_l(x1, x1, (r)); x1 ^= x0; }
    TF_R(13) TF_R(15) TF_R(26) TF_R(6)
    x0 += ks1; x1 += ks2 + 1u;
    TF_R(17) TF_R(29) TF_R(16) TF_R(24)
    x0 += ks2; x1 += 2u;
    TF_R(13) TF_R(15) TF_R(26) TF_R(6)
    x0 += 0u;  x1 += ks1 + 3u;
    TF_R(17) TF_R(29) TF_R(16) TF_R(24)
    x0 += ks1; x1 += ks2 + 4u;
    TF_R(13) TF_R(15) TF_R(26) TF_R(6)
    x0 += ks2; x1 += 5u;
#undef TF_R
    y0 = x0; y1 = x1;
}
__device__ __forceinline__ bool jax_keep(u32 bits) {
    float u = __uint_as_float((bits >> 9) | 0x3F800000u) - 1.0f;
    return u < 0.7f;
}

// ---------------------------------------------------------------------------
// Flash attention, fp32 via packed FFMA2, inline partitionable-threefry mask.
// CTA = (batch b, 64 q rows). 256 threads: tm = tid>>5 (0..7), tn = tid&31.
// Thread: S rows 8tm+i (i<8), S cols 4tn+j (j<4); O cols 4tn+j.
// ---------------------------------------------------------------------------
__global__ __launch_bounds__(NT, 1) void attn_kernel(
    const float* __restrict__ q, const float* __restrict__ k,
    const float* __restrict__ v, const float* __restrict__ sf,
    float* __restrict__ out) {

    extern __shared__ float sm[];
    float* sQt = sm;                    // [128][QS]
    float* sKt = sQt + Dd * QS;         // [128][KS]  (col XOR-swizzled per d-group)
    float* sV  = sKt + Dd * KS;         // [128][VS]
    float* sPt = sV + BN * VS;          // [128][PS]  P^T masked

    const int tid = threadIdx.x;
    const int tm  = tid >> 5;           // 0..7
    const int tn  = tid & 31;           // 0..31
    const int b   = blockIdx.y;
    const int q0  = blockIdx.x * BM;
    const float scale = sf[b];

    // ---- stage Q (once), transposed + pre-scaled ----
    {
        const float* qb = q + ((size_t)b * SQ + q0) * Dd;
#pragma unroll
        for (int it = 0; it < 32; ++it) {
            int idx = it * NT + tid;            // 0..8191
            int r = idx >> 7;                   // 0..63
            int d = idx & 127;
            sQt[d * QS + r] = qb[idx] * scale;
        }
    }

    u64 acc[4][4];
    float m_i[8], l_i[8];
#pragma unroll
    for (int ip = 0; ip < 4; ++ip)
#pragma unroll
        for (int j = 0; j < 4; ++j) acc[ip][j] = 0ull;
#pragma unroll
    for (int i = 0; i < 8; ++i) { m_i[i] = -INFINITY; l_i[i] = 0.f; }

    for (int kv0 = 0; kv0 < SKV; kv0 += BN) {
        __syncthreads();    // previous PV / Q stage complete

        // ---- stage K transposed with XOR swizzle; V row-major ----
        {
            const float4* kb4 = (const float4*)(k + ((size_t)b * SKV + kv0) * Dd);
#pragma unroll
            for (int it = 0; it < 16; ++it) {
                int fidx = it * NT + tid;       // 0..4095
                int r  = fidx >> 5;             // kv row 0..127
                int c4 = fidx & 31;             // d-group 0..31
                float4 t = kb4[fidx];
                int cs = r ^ ((c4 & 7) << 2);   // swizzled column
                float* dst = sKt + (c4 << 2) * KS + cs;
                dst[0 * KS] = t.x; dst[1 * KS] = t.y;
                dst[2 * KS] = t.z; dst[3 * KS] = t.w;
            }
            const float4* vb4 = (const float4*)(v + ((size_t)b * SKV + kv0) * Dd);
#pragma unroll
            for (int it = 0; it < 16; ++it) {
                int fidx = it * NT + tid;
                int r  = fidx >> 5;
                int c4 = fidx & 31;
                *(float4*)(sV + r * VS + (c4 << 2)) = vb4[fidx];
            }
        }
        __syncthreads();

        // ---- S = Q@K^T via FFMA2 ----
        u64 s2[4][4];
#pragma unroll
        for (int ip = 0; ip < 4; ++ip)
#pragma unroll
            for (int j = 0; j < 4; ++j) s2[ip][j] = 0ull;

#pragma unroll 4
        for (int d = 0; d < Dd; ++d) {
            const u64* qp = (const u64*)(sQt + d * QS + (tm << 3));
            u64 q01 = qp[0], q23 = qp[1], q45 = qp[2], q67 = qp[3];
            int cs = (tn ^ ((d >> 2) & 7)) << 2;
            float4 kf = *(const float4*)(sKt + d * KS + cs);
            u64 k0 = pk2(kf.x, kf.x), k1 = pk2(kf.y, kf.y);
            u64 k2 = pk2(kf.z, kf.z), k3 = pk2(kf.w, kf.w);
            s2[0][0] = ffma2(q01, k0, s2[0][0]);
            s2[0][1] = ffma2(q01, k1, s2[0][1]);
            s2[0][2] = ffma2(q01, k2, s2[0][2]);
            s2[0][3] = ffma2(q01, k3, s2[0][3]);
            s2[1][0] = ffma2(q23, k0, s2[1][0]);
            s2[1][1] = ffma2(q23, k1, s2[1][1]);
            s2[1][2] = ffma2(q23, k2, s2[1][2]);
            s2[1][3] = ffma2(q23, k3, s2[1][3]);
            s2[2][0] = ffma2(q45, k0, s2[2][0]);
            s2[2][1] = ffma2(q45, k1, s2[2][1]);
            s2[2][2] = ffma2(q45, k2, s2[2][2]);
            s2[2][3] = ffma2(q45, k3, s2[2][3]);
            s2[3][0] = ffma2(q67, k0, s2[3][0]);
            s2[3][1] = ffma2(q67, k1, s2[3][1]);
            s2[3][2] = ffma2(q67, k2, s2[3][2]);
            s2[3][3] = ffma2(q67, k3, s2[3][3]);
        }

        // ---- online softmax ----
        float p[8][4];
#pragma unroll
        for (int ip = 0; ip < 4; ++ip)
#pragma unroll
            for (int j = 0; j < 4; ++j)
                upk2(s2[ip][j], p[2 * ip][j], p[2 * ip + 1][j]);

        float fac[8];
#pragma unroll
        for (int i = 0; i < 8; ++i) {
            float mx = fmaxf(fmaxf(p[i][0], p[i][1]), fmaxf(p[i][2], p[i][3]));
#pragma unroll
            for (int off = 16; off >= 1; off >>= 1)
                mx = fmaxf(mx, __shfl_xor_sync(0xffffffffu, mx, off));
            float mnew = fmaxf(m_i[i], mx);
            fac[i] = __expf(m_i[i] - mnew);
            m_i[i] = mnew;
            float rs = 0.f;
#pragma unroll
            for (int j = 0; j < 4; ++j) {
                p[i][j] = __expf(p[i][j] - mnew);
                rs += p[i][j];
            }
#pragma unroll
            for (int off = 16; off >= 1; off >>= 1)
                rs += __shfl_xor_sync(0xffffffffu, rs, off);
            l_i[i] = l_i[i] * fac[i] + rs;
        }
        // rescale acc
#pragma unroll
        for (int ip = 0; ip < 4; ++ip) {
            u64 f2 = pk2(fac[2 * ip], fac[2 * ip + 1]);
#pragma unroll
            for (int j = 0; j < 4; ++j) acc[ip][j] = fmul2(acc[ip][j], f2);
        }

        // ---- inline dropout mask (jax partitionable threefry, key 42) ----
        {
            u32 eBase = ((u32)(b * SQ + q0 + (tm << 3))) * (u32)SKV
                      + (u32)(kv0 + (tn << 2));
#pragma unroll
            for (int i = 0; i < 8; ++i) {
                u32 eRow = eBase + (u32)i * (u32)SKV;
#pragma unroll
                for (int j = 0; j < 4; ++j) {
                    u32 y0, y1;
                    threefry_0_42(0u, eRow + (u32)j, y0, y1);
                    if (!jax_keep(y0 ^ y1)) p[i][j] = 0.f;
                }
            }
        }

        // ---- write masked P^T ----
#pragma unroll
        for (int j = 0; j < 4; ++j) {
            int c = (tn << 2) + j;
            *(float4*)(sPt + c * PS + (tm << 3)) =
                make_float4(p[0][j], p[1][j], p[2][j], p[3][j]);
            *(float4*)(sPt + c * PS + (tm << 3) + 4) =
                make_float4(p[4][j], p[5][j], p[6][j], p[7][j]);
        }
        __syncthreads();

        // ---- acc += P^T' @ V via FFMA2 ----
#pragma unroll 4
        for (int n = 0; n < BN; ++n) {
            const u64* pp = (const u64*)(sPt + n * PS + (tm << 3));
            u64 p01 = pp[0], p23 = pp[1], p45 = pp[2], p67 = pp[3];
            float4 vf = *(const float4*)(sV + n * VS + (tn << 2));
            u64 v0 = pk2(vf.x, vf.x), v1 = pk2(vf.y, vf.y);
            u64 v2 = pk2(vf.z, vf.z), v3 = pk2(vf.w, vf.w);
            acc[0][0] = ffma2(p01, v0, acc[0][0]);
            acc[0][1] = ffma2(p01, v1, acc[0][1]);
            acc[0][2] = ffma2(p01, v2, acc[0][2]);
            acc[0][3] = ffma2(p01, v3, acc[0][3]);
            acc[1][0] = ffma2(p23, v0, acc[1][0]);
            acc[1][1] = ffma2(p23, v1, acc[1][1]);
            acc[1][2] = ffma2(p23, v2, acc[1][2]);
            acc[1][3] = ffma2(p23, v3, acc[1][3]);
            acc[2][0] = ffma2(p45, v0, acc[2][0]);
            acc[2][1] = ffma2(p45, v1, acc[2][1]);
            acc[2][2] = ffma2(p45, v2, acc[2][2]);
            acc[3][0] = ffma2(p67, v0, acc[3][0]);
            acc[2][3] = ffma2(p45, v3, acc[2][3]);
            acc[3][1] = ffma2(p67, v1, acc[3][1]);
            acc[3][2] = ffma2(p67, v2, acc[3][2]);
            acc[3][3] = ffma2(p67, v3, acc[3][3]);
        }
    }

    // ---- epilogue: out = acc / (l * 0.7) ----
#pragma unroll
    for (int ip = 0; ip < 4; ++ip) {
        float inv0 = 1.0f / (l_i[2 * ip] * 0.7f);
        float inv1 = 1.0f / (l_i[2 * ip + 1] * 0.7f);
        float lo[4], hi[4];
#pragma unroll
        for (int j = 0; j < 4; ++j) upk2(acc[ip][j], lo[j], hi[j]);
        int r0 = q0 + (tm << 3) + 2 * ip;
        float* o0 = out + ((size_t)b * SQ + r0) * Dd + (tn << 2);
        float* o1 = o0 + Dd;
        *(float4*)o0 = make_float4(lo[0] * inv0, lo[1] * inv0, lo[2] * inv0, lo[3] * inv0);
        *(float4*)o1 = make_float4(hi[0] * inv1, hi[1] * inv1, hi[2] * inv1, hi[3] * inv1);
    }
}

// ---------------------------------------------------------------------------
extern "C" void kernel_launch(void* const* d_in, const int* in_sizes, int n_in,
                              void* d_out, int out_size) {
    const float* q  = (const float*)d_in[0];
    const float* k  = (const float*)d_in[1];
    const float* v  = (const float*)d_in[2];
    const float* sf = (const float*)d_in[3];
    float* out = (float*)d_out;

    size_t smem_bytes = (size_t)(Dd * QS + Dd * KS + BN * VS + BN * PS) * 4;
    cudaFuncSetAttribute(attn_kernel, cudaFuncAttributeMaxDynamicSharedMemorySize,
                         (int)smem_bytes);
    dim3 grid(SQ / BM, Bz);
    attn_kernel<<<grid, NT, smem_bytes>>>(q, k, v, sf, out);
}

// round 4
// speedup vs baseline: 1.8094x; 1.1050x over previous
#include <cuda_runtime.h>
#include <cstdint>
#include <math.h>

#define Bz   32
#define SQ   2048
#define SKV  2048
#define Dd   128
#define BM   64
#define BN   128
#define NT   256

#define QS 68      // sQt stride [d][row64]
#define KS 132     // sKt stride [d][kv128]  (16B-aligned: 528B)
#define VS 132     // sV  stride [n][d128]
#define PS 68      // sPt stride [col128][row64]

typedef unsigned long long u64;
typedef unsigned int u32;

// 32 MB static: K pre-transposed to [B][D][SKV]
__device__ float g_kt[(size_t)Bz * Dd * SKV];

// ---------------- f32x2 packed helpers ----------------
__device__ __forceinline__ u64 ffma2(u64 a, u64 b, u64 c) {
    u64 d; asm("fma.rn.f32x2 %0, %1, %2, %3;" : "=l"(d) : "l"(a), "l"(b), "l"(c));
    return d;
}
__device__ __forceinline__ u64 fmul2(u64 a, u64 b) {
    u64 d; asm("mul.rn.f32x2 %0, %1, %2;" : "=l"(d) : "l"(a), "l"(b));
    return d;
}
__device__ __forceinline__ u64 pk2(float lo, float hi) {
    u64 d; asm("mov.b64 %0, {%1, %2};" : "=l"(d)
               : "r"(__float_as_uint(lo)), "r"(__float_as_uint(hi)));
    return d;
}
__device__ __forceinline__ void upk2(u64 v, float& lo, float& hi) {
    u32 a, b; asm("mov.b64 {%0, %1}, %2;" : "=r"(a), "=r"(b) : "l"(v));
    lo = __uint_as_float(a); hi = __uint_as_float(b);
}

// ---------------- cp.async helpers ----------------
__device__ __forceinline__ void cpa16(u32 dst, const float* src) {
    asm volatile("cp.async.cg.shared.global [%0], [%1], 16;" :: "r"(dst), "l"(src));
}
#define CP_COMMIT() asm volatile("cp.async.commit_group;" ::: "memory")
#define CP_WAIT0()  asm volatile("cp.async.wait_group 0;" ::: "memory")
#define CP_WAIT1()  asm volatile("cp.async.wait_group 1;" ::: "memory")

// ---------------- Threefry-2x32-20, key=(0,42) ----------------
__device__ __forceinline__ void threefry_0_42(u32 x0, u32 x1, u32& y0, u32& y1) {
    const u32 ks1 = 42u;
    const u32 ks2 = 0x1BD11BDAu ^ 42u;
    x1 += ks1;
#define TF_R(r) { x0 += x1; x1 = __funnelshift_l(x1, x1, (r)); x1 ^= x0; }
    TF_R(13) TF_R(15) TF_R(26) TF_R(6)
    x0 += ks1; x1 += ks2 + 1u;
    TF_R(17) TF_R(29) TF_R(16) TF_R(24)
    x0 += ks2; x1 += 2u;
    TF_R(13) TF_R(15) TF_R(26) TF_R(6)
    x0 += 0u;  x1 += ks1 + 3u;
    TF_R(17) TF_R(29) TF_R(16) TF_R(24)
    x0 += ks1; x1 += ks2 + 4u;
    TF_R(13) TF_R(15) TF_R(26) TF_R(6)
    x0 += ks2; x1 += 5u;
#undef TF_R
    y0 = x0; y1 = x1;
}
__device__ __forceinline__ bool jax_keep(u32 bits) {
    float u = __uint_as_float((bits >> 9) | 0x3F800000u) - 1.0f;
    return u < 0.7f;
}

// ---------------------------------------------------------------------------
// K transpose: g_kt[b][d][s] = k[b][s][d]
// ---------------------------------------------------------------------------
__global__ __launch_bounds__(256, 4) void transpose_k_kernel(const float* __restrict__ k) {
    __shared__ float t[32][33];
    int b  = blockIdx.z;
    int s0 = blockIdx.x << 5;
    int d0 = blockIdx.y << 5;
    const float* kb = k + ((size_t)b * SKV + s0) * Dd + d0;
#pragma unroll
    for (int r = threadIdx.y; r < 32; r += 8)
        t[r][threadIdx.x] = kb[r * Dd + threadIdx.x];
    __syncthreads();
    float* kt = g_kt + ((size_t)b * Dd + d0) * SKV + s0;
#pragma unroll
    for (int r = threadIdx.y; r < 32; r += 8)
        kt[r * SKV + threadIdx.x] = t[threadIdx.x][r];
}

// ---------------------------------------------------------------------------
// Flash attention, fp32 FFMA2, inline threefry mask, cp.async K/V pipeline.
// CTA = (batch b, 64 q rows). 256 threads: tm = tid>>5 (0..7), tn = tid&31.
// Thread: S rows 8tm+i (i<8), S cols 4tn+j (j<4); O cols 4tn+j.
// ---------------------------------------------------------------------------
__global__ __launch_bounds__(NT, 1) void attn_kernel(
    const float* __restrict__ q, const float* __restrict__ v,
    const float* __restrict__ sf, float* __restrict__ out) {

    extern __shared__ float sm[];
    float* sQt = sm;                    // [128][QS]
    float* sKt = sQt + Dd * QS;         // [128][KS]  d-major, from g_kt
    float* sV  = sKt + Dd * KS;         // [128][VS]
    float* sPt = sV + BN * VS;          // [128][PS]  P^T masked

    const int tid = threadIdx.x;
    const int tm  = tid >> 5;           // 0..7
    const int tn  = tid & 31;           // 0..31
    const int b   = blockIdx.y;
    const int q0  = blockIdx.x * BM;
    const float scale = sf[b];

    const float* ktb = g_kt + (size_t)b * Dd * SKV;     // [d][s]
    const float* vb  = v + (size_t)b * SKV * Dd;        // [s][d]

    // ---- prologue: start K(0) copy ----
    {
        u32 dK = (u32)__cvta_generic_to_shared(sKt);
#pragma unroll
        for (int it = 0; it < 16; ++it) {
            int id = it * NT + tid;             // 0..4095
            int d  = id >> 5;                   // 0..127
            int c  = (id & 31) << 2;            // float offset
            cpa16(dK + (u32)(d * KS + c) * 4u, ktb + (size_t)d * SKV + 0 + c);
        }
        CP_COMMIT();
    }

    // ---- stage Q (once), transposed + pre-scaled ----
    {
        const float* qb = q + ((size_t)b * SQ + q0) * Dd;
#pragma unroll
        for (int it = 0; it < 32; ++it) {
            int idx = it * NT + tid;            // 0..8191
            int r = idx >> 7;                   // 0..63
            int d = idx & 127;
            sQt[d * QS + r] = qb[idx] * scale;
        }
    }

    u64 acc[4][4];
    float m_i[8], l_i[8];
#pragma unroll
    for (int ip = 0; ip < 4; ++ip)
#pragma unroll
        for (int j = 0; j < 4; ++j) acc[ip][j] = 0ull;
#pragma unroll
    for (int i = 0; i < 8; ++i) { m_i[i] = -INFINITY; l_i[i] = 0.f; }

    u32 dV = (u32)__cvta_generic_to_shared(sV);
    u32 dK = (u32)__cvta_generic_to_shared(sKt);

    for (int kv0 = 0; kv0 < SKV; kv0 += BN) {
        // K(i) landed (only it may be pending at this point)
        CP_WAIT0();
        __syncthreads();        // K visible to all; prev PV done -> sV free

        // issue V(i); waited before PV (hidden by QK)
        {
#pragma unroll
            for (int it = 0; it < 16; ++it) {
                int id = it * NT + tid;
                int r  = id >> 5;
                int c  = (id & 31) << 2;
                cpa16(dV + (u32)(r * VS + c) * 4u,
                      vb + (size_t)(kv0 + r) * Dd + c);
            }
            CP_COMMIT();
        }

        // ---- S = Q@K^T via FFMA2 ----
        u64 s2[4][4];
#pragma unroll
        for (int ip = 0; ip < 4; ++ip)
#pragma unroll
            for (int j = 0; j < 4; ++j) s2[ip][j] = 0ull;

#pragma unroll 4
        for (int d = 0; d < Dd; ++d) {
            const u64* qp = (const u64*)(sQt + d * QS + (tm << 3));
            u64 q01 = qp[0], q23 = qp[1], q45 = qp[2], q67 = qp[3];
            float4 kf = *(const float4*)(sKt + d * KS + (tn << 2));
            u64 k0 = pk2(kf.x, kf.x), k1 = pk2(kf.y, kf.y);
            u64 k2 = pk2(kf.z, kf.z), k3 = pk2(kf.w, kf.w);
            s2[0][0] = ffma2(q01, k0, s2[0][0]);
            s2[0][1] = ffma2(q01, k1, s2[0][1]);
            s2[0][2] = ffma2(q01, k2, s2[0][2]);
            s2[0][3] = ffma2(q01, k3, s2[0][3]);
            s2[1][0] = ffma2(q23, k0, s2[1][0]);
            s2[1][1] = ffma2(q23, k1, s2[1][1]);
            s2[1][2] = ffma2(q23, k2, s2[1][2]);
            s2[1][3] = ffma2(q23, k3, s2[1][3]);
            s2[2][0] = ffma2(q45, k0, s2[2][0]);
            s2[2][1] = ffma2(q45, k1, s2[2][1]);
            s2[2][2] = ffma2(q45, k2, s2[2][2]);
            s2[2][3] = ffma2(q45, k3, s2[2][3]);
            s2[3][0] = ffma2(q67, k0, s2[3][0]);
            s2[3][1] = ffma2(q67, k1, s2[3][1]);
            s2[3][2] = ffma2(q67, k2, s2[3][2]);
            s2[3][3] = ffma2(q67, k3, s2[3][3]);
        }

        // ---- online softmax ----
        float p[8][4];
#pragma unroll
        for (int ip = 0; ip < 4; ++ip)
#pragma unroll
            for (int j = 0; j < 4; ++j)
                upk2(s2[ip][j], p[2 * ip][j], p[2 * ip + 1][j]);

        float fac[8];
#pragma unroll
        for (int i = 0; i < 8; ++i) {
            float mx = fmaxf(fmaxf(p[i][0], p[i][1]), fmaxf(p[i][2], p[i][3]));
#pragma unroll
            for (int off = 16; off >= 1; off >>= 1)
                mx = fmaxf(mx, __shfl_xor_sync(0xffffffffu, mx, off));
            float mnew = fmaxf(m_i[i], mx);
            fac[i] = __expf(m_i[i] - mnew);
            m_i[i] = mnew;
            float rs = 0.f;
#pragma unroll
            for (int j = 0; j < 4; ++j) {
                p[i][j] = __expf(p[i][j] - mnew);
                rs += p[i][j];
            }
#pragma unroll
            for (int off = 16; off >= 1; off >>= 1)
                rs += __shfl_xor_sync(0xffffffffu, rs, off);
            l_i[i] = l_i[i] * fac[i] + rs;
        }
#pragma unroll
        for (int ip = 0; ip < 4; ++ip) {
            u64 f2 = pk2(fac[2 * ip], fac[2 * ip + 1]);
#pragma unroll
            for (int j = 0; j < 4; ++j) acc[ip][j] = fmul2(acc[ip][j], f2);
        }

        // ---- inline dropout mask (jax partitionable threefry, key 42) ----
        {
            u32 eBase = ((u32)(b * SQ + q0 + (tm << 3))) * (u32)SKV
                      + (u32)(kv0 + (tn << 2));
#pragma unroll
            for (int i = 0; i < 8; ++i) {
                u32 eRow = eBase + (u32)i * (u32)SKV;
#pragma unroll
                for (int j = 0; j < 4; ++j) {
                    u32 y0, y1;
                    threefry_0_42(0u, eRow + (u32)j, y0, y1);
                    if (!jax_keep(y0 ^ y1)) p[i][j] = 0.f;
                }
            }
        }

        // ---- write masked P^T ----
#pragma unroll
        for (int j = 0; j < 4; ++j) {
            int c = (tn << 2) + j;
            *(float4*)(sPt + c * PS + (tm << 3)) =
                make_float4(p[0][j], p[1][j], p[2][j], p[3][j]);
            *(float4*)(sPt + c * PS + (tm << 3) + 4) =
                make_float4(p[4][j], p[5][j], p[6][j], p[7][j]);
        }
        __syncthreads();        // all QK reads of sKt done; P visible

        // issue K(i+1) into sKt (hidden by PV)
        if (kv0 + BN < SKV) {
#pragma unroll
            for (int it = 0; it < 16; ++it) {
                int id = it * NT + tid;
                int d  = id >> 5;
                int c  = (id & 31) << 2;
                cpa16(dK + (u32)(d * KS + c) * 4u,
                      ktb + (size_t)d * SKV + (kv0 + BN) + c);
            }
            CP_COMMIT();
            CP_WAIT1();         // V(i) done; K(i+1) may fly
        } else {
            CP_WAIT0();         // V(i) done
        }
        __syncthreads();        // V visible to all

        // ---- acc += P^T' @ V via FFMA2 ----
#pragma unroll 4
        for (int n = 0; n < BN; ++n) {
            const u64* pp = (const u64*)(sPt + n * PS + (tm << 3));
            u64 p01 = pp[0], p23 = pp[1], p45 = pp[2], p67 = pp[3];
            float4 vf = *(const float4*)(sV + n * VS + (tn << 2));
            u64 v0 = pk2(vf.x, vf.x), v1 = pk2(vf.y, vf.y);
            u64 v2 = pk2(vf.z, vf.z), v3 = pk2(vf.w, vf.w);
            acc[0][0] = ffma2(p01, v0, acc[0][0]);
            acc[0][1] = ffma2(p01, v1, acc[0][1]);
            acc[0][2] = ffma2(p01, v2, acc[0][2]);
            acc[0][3] = ffma2(p01, v3, acc[0][3]);
            acc[1][0] = ffma2(p23, v0, acc[1][0]);
            acc[1][1] = ffma2(p23, v1, acc[1][1]);
            acc[1][2] = ffma2(p23, v2, acc[1][2]);
            acc[1][3] = ffma2(p23, v3, acc[1][3]);
            acc[2][0] = ffma2(p45, v0, acc[2][0]);
            acc[2][1] = ffma2(p45, v1, acc[2][1]);
            acc[2][2] = ffma2(p45, v2, acc[2][2]);
            acc[3][0] = ffma2(p67, v0, acc[3][0]);
            acc[2][3] = ffma2(p45, v3, acc[2][3]);
            acc[3][1] = ffma2(p67, v1, acc[3][1]);
            acc[3][2] = ffma2(p67, v2, acc[3][2]);
            acc[3][3] = ffma2(p67, v3, acc[3][3]);
        }
    }

    // ---- epilogue: out = acc / (l * 0.7) ----
#pragma unroll
    for (int ip = 0; ip < 4; ++ip) {
        float inv0 = 1.0f / (l_i[2 * ip] * 0.7f);
        float inv1 = 1.0f / (l_i[2 * ip + 1] * 0.7f);
        float lo[4], hi[4];
#pragma unroll
        for (int j = 0; j < 4; ++j) upk2(acc[ip][j], lo[j], hi[j]);
        int r0 = q0 + (tm << 3) + 2 * ip;
        float* o0 = out + ((size_t)b * SQ + r0) * Dd + (tn << 2);
        float* o1 = o0 + Dd;
        *(float4*)o0 = make_float4(lo[0] * inv0, lo[1] * inv0, lo[2] * inv0, lo[3] * inv0);
        *(float4*)o1 = make_float4(hi[0] * inv1, hi[1] * inv1, hi[2] * inv1, hi[3] * inv1);
    }
}

// ---------------------------------------------------------------------------
extern "C" void kernel_launch(void* const* d_in, const int* in_sizes, int n_in,
                              void* d_out, int out_size) {
    const float* q  = (const float*)d_in[0];
    const float* k  = (const float*)d_in[1];
    const float* v  = (const float*)d_in[2];
    const float* sf = (const float*)d_in[3];
    float* out = (float*)d_out;

    // 1) K -> g_kt transpose  [B][D][SKV]
    {
        dim3 grid(SKV / 32, Dd / 32, Bz);
        transpose_k_kernel<<<grid, dim3(32, 8)>>>(k);
    }

    // 2) Flash attention
    size_t smem_bytes = (size_t)(Dd * QS + Dd * KS + BN * VS + BN * PS) * 4;
    cudaFuncSetAttribute(attn_kernel, cudaFuncAttributeMaxDynamicSharedMemorySize,
                         (int)smem_bytes);
    dim3 grid(SQ / BM, Bz);
    attn_kernel<<<grid, NT, smem_bytes>>>(q, v, sf, out);
}